// round 1
// baseline (speedup 1.0000x reference)
#include <cuda_runtime.h>
#include <math.h>

#define BB     4
#define SS     2048
#define DD     1024
#define NIN    8192
#define NPROC  4096
#define DR     256
#define HH     512
#define KIN    4096
#define KPROC  2048

// ---------------- scratch (static device memory; no allocs) ----------------
__device__ float g_gc[BB * DD];
__device__ float g_h[BB * HH];
__device__ float g_query[BB * DR];
__device__ float g_logits[BB * NIN];
__device__ int   g_iidx[BB * KIN];
__device__ int   g_pidx[BB * KPROC];
__device__ float g_scores[BB * NPROC];
__device__ float g_sel[(size_t)BB * SS * KIN];     // 128 MB
__device__ float g_Wg[(size_t)BB * NPROC * KIN];   // 256 MB
__device__ float g_proc[(size_t)BB * SS * NPROC];  // 128 MB
__device__ float g_sp[(size_t)BB * SS * KPROC];    //  64 MB

__device__ __forceinline__ float gelu_f(float x) {
    return 0.5f * x * (1.0f + erff(x * 0.70710678118654752440f));
}

// ---------------- 1) global context: max over S ----------------
__global__ void k_gcmax(const float* __restrict__ x) {
    int b = blockIdx.y;
    int d = blockIdx.x * 256 + threadIdx.x;
    const float* p = x + (size_t)b * SS * DD + d;
    float m = -3.4e38f;
    for (int s = 0; s < SS; s++) m = fmaxf(m, p[(size_t)s * DD]);
    g_gc[b * DD + d] = m;
}

// ---------------- small matvec: warp per output ----------------
// out[b*Nout+j] = act( scale * dot(W[j,:], in[b,:]) + bias[j] )
__global__ void k_matvec(const float* __restrict__ W, const float* __restrict__ bias,
                         const float* __restrict__ in, float* __restrict__ out,
                         int Nout, int Kd, float scale, int act) {
    int o = blockIdx.x * 8 + (threadIdx.x >> 5);
    int lane = threadIdx.x & 31;
    if (o >= BB * Nout) return;
    int b = o / Nout, j = o - b * Nout;
    const float* w = W + (size_t)j * Kd;
    const float* v = in + (size_t)b * Kd;
    float s = 0.f;
    for (int d = lane; d < Kd; d += 32) s = fmaf(w[d], v[d], s);
#pragma unroll
    for (int off = 16; off; off >>= 1) s += __shfl_xor_sync(0xffffffffu, s, off);
    if (lane == 0) {
        s = s * scale + (bias ? bias[j] : 0.f);
        if (act) s = gelu_f(s);
        out[o] = s;
    }
}

// ---------------- layernorm over HH=512, one block per batch row ----------------
__global__ void k_ln(const float* __restrict__ gamma, const float* __restrict__ beta) {
    int b = blockIdx.x, j = threadIdx.x;
    __shared__ float sh[16];
    __shared__ float s_mu, s_var;
    float v = g_h[b * HH + j];

    float s = v;
#pragma unroll
    for (int o = 16; o; o >>= 1) s += __shfl_xor_sync(0xffffffffu, s, o);
    if ((j & 31) == 0) sh[j >> 5] = s;
    __syncthreads();
    if (j == 0) {
        float t = 0.f;
        for (int w = 0; w < 16; w++) t += sh[w];
        s_mu = t / HH;
    }
    __syncthreads();
    float d = v - s_mu;
    float s2 = d * d;
#pragma unroll
    for (int o = 16; o; o >>= 1) s2 += __shfl_xor_sync(0xffffffffu, s2, o);
    __syncthreads();   // protect sh reuse
    if ((j & 31) == 0) sh[j >> 5] = s2;
    __syncthreads();
    if (j == 0) {
        float t = 0.f;
        for (int w = 0; w < 16; w++) t += sh[w];
        s_var = t / HH;
    }
    __syncthreads();
    g_h[b * HH + j] = d * rsqrtf(s_var + 1e-5f) * gamma[j] + beta[j];
}

// ---------------- exact top-k set selection via counting rank ----------------
// rank(i) = #{j : v[j] > v[i]  ||  (v[j]==v[i] && j<i)}  (matches lax.top_k order)
__global__ void k_select(const float* __restrict__ vals, int n, int k, int* __restrict__ idx) {
    int b = blockIdx.y;
    const float* v = vals + (size_t)b * n;
    int i = blockIdx.x * 256 + threadIdx.x;
    float vi = v[i];
    __shared__ float sv[256];
    int r = 0;
    for (int t0 = 0; t0 < n; t0 += 256) {
        sv[threadIdx.x] = v[t0 + threadIdx.x];
        __syncthreads();
#pragma unroll 8
        for (int t = 0; t < 256; t++) {
            float vj = sv[t];
            int j = t0 + t;
            r += (vj > vi) || (vj == vi && j < i);
        }
        __syncthreads();
    }
    if (r < k) idx[(size_t)b * k + r] = i;
}

// ---------------- gather process weight columns: Wg[b][p][k] = PW[p][iidx[b][k]] ----------------
__global__ void k_gatherW(const float* __restrict__ PW) {
    int b = blockIdx.z;
    int k0 = blockIdx.x * 256;
    int p0 = blockIdx.y * 32;
    __shared__ int si[256];
    si[threadIdx.x] = g_iidx[(size_t)b * KIN + k0 + threadIdx.x];
    __syncthreads();
    int col = si[threadIdx.x];
#pragma unroll 4
    for (int pp = 0; pp < 32; pp++) {
        int p = p0 + pp;
        g_Wg[((size_t)b * NPROC + p) * KIN + k0 + threadIdx.x] = PW[(size_t)p * NIN + col];
    }
}

// ---------------- scores[b][p] = mean_s proc[b][s][p] ----------------
__global__ void k_scores() {
    int b = blockIdx.y;
    int p = blockIdx.x * 256 + threadIdx.x;
    const float* base = g_proc + (size_t)b * SS * NPROC + p;
    float s = 0.f;
    for (int t = 0; t < SS; t++) s += base[(size_t)t * NPROC];
    g_scores[b * NPROC + p] = s * (1.0f / SS);
}

// ---------------- gather selected proc columns: sp[b][s][k] = proc[b][s][pidx[b][k]] ----------------
__global__ void k_gathersp() {
    int b = blockIdx.z, s = blockIdx.y;
    int k = blockIdx.x * 256 + threadIdx.x;
    int pi = g_pidx[(size_t)b * KPROC + k];
    g_sp[((size_t)b * SS + s) * KPROC + k] = g_proc[((size_t)b * SS + s) * NPROC + pi];
}

// ---------------- tiled SGEMM: C[m,n] = act( sum_k A[m,k]*B(n or k row)[..] ) ----------------
// BT=true : B is [N,K] row-major (NT gemm), optional row gather idx over n
// BT=false: B is [K,N] row-major (NN gemm), optional row gather idx over k
template <bool BT, bool ACT>
__global__ void __launch_bounds__(256, 2)
k_gemm(const float* __restrict__ A, const float* __restrict__ Bm,
       const int* __restrict__ bIdx, float* __restrict__ Cm,
       int K, int lda, int ldb, int ldc,
       size_t aBatch, size_t bBatch, size_t cBatch, int idxBatch) {
    const int bz = blockIdx.z;
    A  += (size_t)bz * aBatch;
    Bm += (size_t)bz * bBatch;
    Cm += (size_t)bz * cBatch;
    const int* idx = bIdx ? bIdx + (size_t)bz * idxBatch : nullptr;

    __shared__ __align__(16) float As[16][132];
    __shared__ __align__(16) float Bs[16][132];

    const int m0 = blockIdx.y * 128, n0 = blockIdx.x * 128;
    const int tid = threadIdx.x;
    const int tm = (tid >> 4) * 8;
    const int tn = (tid & 15) * 8;

    float acc[8][8];
#pragma unroll
    for (int i = 0; i < 8; i++)
#pragma unroll
        for (int j = 0; j < 8; j++) acc[i][j] = 0.f;

    // hoist gather rows for NT mode (independent of k0)
    int ntrow[2];
    if (BT) {
#pragma unroll
        for (int q = 0; q < 2; q++) {
            int i = tid + q * 256;
            int row = i >> 2;
            ntrow[q] = idx ? idx[n0 + row] : (n0 + row);
        }
    }

    for (int k0 = 0; k0 < K; k0 += 16) {
        // ---- load A tile [128m x 16k], store transposed As[k][m]
#pragma unroll
        for (int q = 0; q < 2; q++) {
            int i = tid + q * 256;
            int row = i >> 2, kq = (i & 3) * 4;
            float4 v = *(const float4*)(A + (size_t)(m0 + row) * lda + k0 + kq);
            As[kq + 0][row] = v.x;
            As[kq + 1][row] = v.y;
            As[kq + 2][row] = v.z;
            As[kq + 3][row] = v.w;
        }
        // ---- load B tile
        if (BT) {
#pragma unroll
            for (int q = 0; q < 2; q++) {
                int i = tid + q * 256;
                int row = i >> 2, kq = (i & 3) * 4;
                float4 v = *(const float4*)(Bm + (size_t)ntrow[q] * ldb + k0 + kq);
                Bs[kq + 0][row] = v.x;
                Bs[kq + 1][row] = v.y;
                Bs[kq + 2][row] = v.z;
                Bs[kq + 3][row] = v.w;
            }
        } else {
#pragma unroll
            for (int q = 0; q < 2; q++) {
                int i = tid + q * 256;
                int row = i >> 5, nq = (i & 31) * 4;
                int r = idx ? idx[k0 + row] : (k0 + row);
                float4 v = *(const float4*)(Bm + (size_t)r * ldb + n0 + nq);
                *(float4*)&Bs[row][nq] = v;
            }
        }
        __syncthreads();

#pragma unroll
        for (int kk = 0; kk < 16; kk++) {
            float a[8], bv[8];
#pragma unroll
            for (int i = 0; i < 8; i++) {
                a[i]  = As[kk][tm + i];
                bv[i] = Bs[kk][tn + i];
            }
#pragma unroll
            for (int i = 0; i < 8; i++)
#pragma unroll
                for (int j = 0; j < 8; j++) acc[i][j] = fmaf(a[i], bv[j], acc[i][j]);
        }
        __syncthreads();
    }

#pragma unroll
    for (int i = 0; i < 8; i++) {
        float* cp = Cm + (size_t)(m0 + tm + i) * ldc + n0 + tn;
        float4 v0, v1;
        v0.x = ACT ? gelu_f(acc[i][0]) : acc[i][0];
        v0.y = ACT ? gelu_f(acc[i][1]) : acc[i][1];
        v0.z = ACT ? gelu_f(acc[i][2]) : acc[i][2];
        v0.w = ACT ? gelu_f(acc[i][3]) : acc[i][3];
        v1.x = ACT ? gelu_f(acc[i][4]) : acc[i][4];
        v1.y = ACT ? gelu_f(acc[i][5]) : acc[i][5];
        v1.z = ACT ? gelu_f(acc[i][6]) : acc[i][6];
        v1.w = ACT ? gelu_f(acc[i][7]) : acc[i][7];
        *(float4*)cp       = v0;
        *(float4*)(cp + 4) = v1;
    }
}

// ---------------- host side ----------------
extern "C" void kernel_launch(void* const* d_in, const int* in_sizes, int n_in,
                              void* d_out, int out_size) {
    const float* x   = (const float*)d_in[0];
    const float* W1  = (const float*)d_in[1];
    const float* b1  = (const float*)d_in[2];
    const float* lng = (const float*)d_in[3];
    const float* lnb = (const float*)d_in[4];
    const float* W2  = (const float*)d_in[5];
    const float* b2  = (const float*)d_in[6];
    const float* NK  = (const float*)d_in[7];
    const float* IP  = (const float*)d_in[8];
    const float* PW  = (const float*)d_in[9];
    const float* PO  = (const float*)d_in[10];
    float* out = (float*)d_out;

    void *p_gc, *p_h, *p_query, *p_logits, *p_iidx, *p_pidx, *p_scores;
    void *p_sel, *p_Wg, *p_proc, *p_sp;
    cudaGetSymbolAddress(&p_gc, g_gc);
    cudaGetSymbolAddress(&p_h, g_h);
    cudaGetSymbolAddress(&p_query, g_query);
    cudaGetSymbolAddress(&p_logits, g_logits);
    cudaGetSymbolAddress(&p_iidx, g_iidx);
    cudaGetSymbolAddress(&p_pidx, g_pidx);
    cudaGetSymbolAddress(&p_scores, g_scores);
    cudaGetSymbolAddress(&p_sel, g_sel);
    cudaGetSymbolAddress(&p_Wg, g_Wg);
    cudaGetSymbolAddress(&p_proc, g_proc);
    cudaGetSymbolAddress(&p_sp, g_sp);

    // 1) global context
    k_gcmax<<<dim3(DD / 256, BB), 256>>>(x);

    // 2) router MLP
    k_matvec<<<(BB * HH) / 8, 256>>>(W1, b1, (const float*)p_gc, (float*)p_h, HH, DD, 1.0f, 1);
    k_ln<<<BB, HH>>>(lng, lnb);
    k_matvec<<<(BB * DR) / 8, 256>>>(W2, b2, (const float*)p_h, (float*)p_query, DR, HH, 1.0f, 0);
    k_matvec<<<(BB * NIN) / 8, 256>>>(NK, nullptr, (const float*)p_query, (float*)p_logits,
                                      NIN, DR, 0.0625f /* 1/sqrt(256) */, 0);

    // 3) input neuron selection (top-4096 of 8192)
    k_select<<<dim3(NIN / 256, BB), 256>>>((const float*)p_logits, NIN, KIN, (int*)p_iidx);

    // 4) selected input activations: sel[b][s][k] = gelu(x[b,s,:] . IP[iidx[b,k],:])
    k_gemm<true, true><<<dim3(KIN / 128, SS / 128, BB), 256>>>(
        x, IP, (const int*)p_iidx, (float*)p_sel,
        DD, DD, DD, KIN,
        (size_t)SS * DD, 0, (size_t)SS * KIN, KIN);

    // 5) gather process weight columns -> Wg[b][p][k]
    k_gatherW<<<dim3(KIN / 256, NPROC / 32, BB), 256>>>(PW);

    // 6) process activations: proc[b][s][p] = gelu(sel[b,s,:] . Wg[b,p,:])
    k_gemm<true, true><<<dim3(NPROC / 128, SS / 128, BB), 256>>>(
        (const float*)p_sel, (const float*)p_Wg, nullptr, (float*)p_proc,
        KIN, KIN, KIN, NPROC,
        (size_t)SS * KIN, (size_t)NPROC * KIN, (size_t)SS * NPROC, 0);

    // 7) scores + process selection (top-2048 of 4096)
    k_scores<<<dim3(NPROC / 256, BB), 256>>>();
    k_select<<<dim3(NPROC / 256, BB), 256>>>((const float*)p_scores, NPROC, KPROC, (int*)p_pidx);

    // 8) gather selected proc columns
    k_gathersp<<<dim3(KPROC / 256, SS, BB), 256>>>();

    // 9) output: out[b][s][d] = sp[b,s,:] . PO[pidx[b,:], d]
    k_gemm<false, false><<<dim3(DD / 128, SS / 128, BB), 256>>>(
        (const float*)p_sp, PO, (const int*)p_pidx, out,
        KPROC, KPROC, DD, DD,
        (size_t)SS * KPROC, 0, (size_t)SS * DD, KPROC);
}

// round 3
// speedup vs baseline: 1.3932x; 1.3932x over previous
#include <cuda_runtime.h>
#include <math.h>
#include <stdint.h>

#define BB     4
#define SS     2048
#define DD     1024
#define NIN    8192
#define NPROC  4096
#define DR     256
#define HH     512
#define KIN    4096
#define KPROC  2048

// ---------------- scratch (static device memory; no allocs) ----------------
__device__ float g_gc[BB * DD];
__device__ float g_h[BB * HH];
__device__ float g_query[BB * DR];
__device__ float g_logits[BB * NIN];
__device__ int   g_iidx[BB * KIN];
__device__ int   g_iidx2[BB * KIN];
__device__ int   g_pidx[BB * KPROC];
__device__ int   g_pidx2[BB * KPROC];
__device__ float g_scores[BB * NPROC];
__device__ float g_sel[(size_t)BB * SS * KIN];     // 128 MB
__device__ float g_Wg[(size_t)BB * NPROC * KIN];   // 256 MB
__device__ float g_proc[(size_t)BB * SS * NPROC];  // 128 MB
__device__ float g_sp[(size_t)BB * SS * KPROC];    //  64 MB
__device__ float g_pot[(size_t)BB * DD * KPROC];   //  32 MB

__device__ __forceinline__ float gelu_f(float x) {
    return 0.5f * x * (1.0f + erff(x * 0.70710678118654752440f));
}
__device__ __forceinline__ uint32_t to_tf32(float a) {
    uint32_t r;
    asm("cvt.rna.tf32.f32 %0, %1;" : "=r"(r) : "f"(a));
    return r;
}

__device__ __forceinline__ uint32_t s2u(const void* p) {
    uint32_t a;
    asm("{ .reg .u64 t; cvta.to.shared.u64 t, %1; cvt.u32.u64 %0, t; }" : "=r"(a) : "l"(p));
    return a;
}
__device__ __forceinline__ void cpa16(uint32_t dst, const float* src) {
    asm volatile("cp.async.cg.shared.global [%0], [%1], 16;" :: "r"(dst), "l"(src));
}
__device__ __forceinline__ void cpacommit() { asm volatile("cp.async.commit_group;" ::: "memory"); }
__device__ __forceinline__ void cpawait1()  { asm volatile("cp.async.wait_group 1;" ::: "memory"); }

__device__ __forceinline__ void mma8(float* c, const uint32_t* a, const uint32_t* b) {
    asm volatile("mma.sync.aligned.m16n8k8.row.col.f32.tf32.tf32.f32 "
        "{%0,%1,%2,%3}, {%4,%5,%6,%7}, {%8,%9}, {%0,%1,%2,%3};"
        : "+f"(c[0]), "+f"(c[1]), "+f"(c[2]), "+f"(c[3])
        : "r"(a[0]), "r"(a[1]), "r"(a[2]), "r"(a[3]), "r"(b[0]), "r"(b[1]));
}

// ============ tensor-core GEMM: C[128m x 128n] per CTA, NT, fp32 in/out ============
// PASSES=3: 3xTF32 (AhBh + AhBl + AlBh) ~ fp32 accuracy. PASSES=1: plain tf32.
// GATH=1: B rows gathered through bIdx[n].
#define LDS_W 36
#define TILE_F (128 * LDS_W)

template <int PASSES, int ACT, int GATH>
__global__ void __launch_bounds__(256, 1)
k_gemm_mma(const float* __restrict__ A, const float* __restrict__ B,
           const int* __restrict__ bIdx, float* __restrict__ C,
           int K, int ldc, size_t aB, size_t bB, size_t cB, int idxB) {
    extern __shared__ float sm[];
    float* As = sm;                  // [2][128][36]
    float* Bs = sm + 2 * TILE_F;     // [2][128][36]

    const int bz = blockIdx.z;
    const int m0 = blockIdx.y * 128, n0 = blockIdx.x * 128;
    A += bz * aB + (size_t)m0 * K;
    B += bz * bB;
    C += bz * cB;

    const int tid = threadIdx.x;
    const int lr = tid >> 3;          // loader row 0..31
    const int lk = (tid & 7) * 4;     // loader k offset (floats)

    const float* ap[4];
    const float* bp[4];
#pragma unroll
    for (int q = 0; q < 4; q++) {
        int r = lr + q * 32;
        ap[q] = A + (size_t)r * K + lk;
        int gr = GATH ? bIdx[(size_t)bz * idxB + n0 + r] : (n0 + r);
        bp[q] = B + (size_t)gr * K + lk;
    }
    uint32_t sA[4], sB[4];
#pragma unroll
    for (int q = 0; q < 4; q++) {
        sA[q] = s2u(&As[(lr + q * 32) * LDS_W + lk]);
        sB[q] = s2u(&Bs[(lr + q * 32) * LDS_W + lk]);
    }

    const int wid = tid >> 5, lane = tid & 31;
    const int wm = (wid & 1) * 64, wn = (wid >> 1) * 32;
    const int qrow = lane >> 2, qk = lane & 3;

    float acc[4][4][4];
#pragma unroll
    for (int mt = 0; mt < 4; mt++)
#pragma unroll
        for (int nt = 0; nt < 4; nt++)
#pragma unroll
            for (int e = 0; e < 4; e++) acc[mt][nt][e] = 0.f;

    const int nc = K >> 5;

    // prologue: 2 stages
#pragma unroll
    for (int st = 0; st < 2; st++) {
#pragma unroll
        for (int q = 0; q < 4; q++) {
            cpa16(sA[q] + st * TILE_F * 4, ap[q] + st * 32);
            cpa16(sB[q] + st * TILE_F * 4, bp[q] + st * 32);
        }
        cpacommit();
    }

    for (int c = 0; c < nc; c++) {
        cpawait1();
        __syncthreads();
        const float* as = As + (c & 1) * TILE_F;
        const float* bs = Bs + (c & 1) * TILE_F;
#pragma unroll
        for (int ks = 0; ks < 4; ks++) {
            const int kb = ks * 8 + qk;
            uint32_t ah[4][4], al[4][4];
#pragma unroll
            for (int mt = 0; mt < 4; mt++) {
                int r = wm + mt * 16 + qrow;
                float a0 = as[r * LDS_W + kb];
                float a1 = as[(r + 8) * LDS_W + kb];
                float a2 = as[r * LDS_W + kb + 4];
                float a3 = as[(r + 8) * LDS_W + kb + 4];
                ah[mt][0] = to_tf32(a0); ah[mt][1] = to_tf32(a1);
                ah[mt][2] = to_tf32(a2); ah[mt][3] = to_tf32(a3);
                if (PASSES == 3) {
                    al[mt][0] = to_tf32(a0 - __uint_as_float(ah[mt][0]));
                    al[mt][1] = to_tf32(a1 - __uint_as_float(ah[mt][1]));
                    al[mt][2] = to_tf32(a2 - __uint_as_float(ah[mt][2]));
                    al[mt][3] = to_tf32(a3 - __uint_as_float(ah[mt][3]));
                }
            }
            uint32_t bh[4][2], bl[4][2];
#pragma unroll
            for (int nt = 0; nt < 4; nt++) {
                int n = wn + nt * 8 + qrow;
                float b0 = bs[n * LDS_W + kb];
                float b1 = bs[n * LDS_W + kb + 4];
                bh[nt][0] = to_tf32(b0); bh[nt][1] = to_tf32(b1);
                if (PASSES == 3) {
                    bl[nt][0] = to_tf32(b0 - __uint_as_float(bh[nt][0]));
                    bl[nt][1] = to_tf32(b1 - __uint_as_float(bh[nt][1]));
                }
            }
#pragma unroll
            for (int mt = 0; mt < 4; mt++)
#pragma unroll
                for (int nt = 0; nt < 4; nt++) {
                    mma8(acc[mt][nt], ah[mt], bh[nt]);
                    if (PASSES == 3) {
                        mma8(acc[mt][nt], ah[mt], bl[nt]);
                        mma8(acc[mt][nt], al[mt], bh[nt]);
                    }
                }
        }
        __syncthreads();
        if (c + 2 < nc) {
            int st = c & 1, k0 = (c + 2) * 32;
#pragma unroll
            for (int q = 0; q < 4; q++) {
                cpa16(sA[q] + st * TILE_F * 4, ap[q] + k0);
                cpa16(sB[q] + st * TILE_F * 4, bp[q] + k0);
            }
            cpacommit();
        } else {
            cpacommit();   // keep group accounting uniform
        }
    }

    // epilogue
#pragma unroll
    for (int mt = 0; mt < 4; mt++) {
#pragma unroll
        for (int nt = 0; nt < 4; nt++) {
            int r = m0 + wm + mt * 16 + qrow;
            int cc = n0 + wn + nt * 8 + qk * 2;
            float2 v0, v1;
            v0.x = ACT ? gelu_f(acc[mt][nt][0]) : acc[mt][nt][0];
            v0.y = ACT ? gelu_f(acc[mt][nt][1]) : acc[mt][nt][1];
            v1.x = ACT ? gelu_f(acc[mt][nt][2]) : acc[mt][nt][2];
            v1.y = ACT ? gelu_f(acc[mt][nt][3]) : acc[mt][nt][3];
            *(float2*)&C[(size_t)r * ldc + cc] = v0;
            *(float2*)&C[(size_t)(r + 8) * ldc + cc] = v1;
        }
    }
}

// ---------------- 1) global context: max over S ----------------
__global__ void k_gcmax(const float* __restrict__ x) {
    int b = blockIdx.y;
    int d = blockIdx.x * 256 + threadIdx.x;
    const float* p = x + (size_t)b * SS * DD + d;
    float m = -3.4e38f;
    for (int s = 0; s < SS; s++) m = fmaxf(m, p[(size_t)s * DD]);
    g_gc[b * DD + d] = m;
}

// ---------------- small matvec: warp per output ----------------
__global__ void k_matvec(const float* __restrict__ W, const float* __restrict__ bias,
                         const float* __restrict__ in, float* __restrict__ out,
                         int Nout, int Kd, float scale, int act) {
    int o = blockIdx.x * 8 + (threadIdx.x >> 5);
    int lane = threadIdx.x & 31;
    if (o >= BB * Nout) return;
    int b = o / Nout, j = o - b * Nout;
    const float* w = W + (size_t)j * Kd;
    const float* v = in + (size_t)b * Kd;
    float s = 0.f;
    for (int d = lane; d < Kd; d += 32) s = fmaf(w[d], v[d], s);
#pragma unroll
    for (int off = 16; off; off >>= 1) s += __shfl_xor_sync(0xffffffffu, s, off);
    if (lane == 0) {
        s = s * scale + (bias ? bias[j] : 0.f);
        if (act) s = gelu_f(s);
        out[o] = s;
    }
}

// ---------------- layernorm over HH=512 ----------------
__global__ void k_ln(const float* __restrict__ gamma, const float* __restrict__ beta) {
    int b = blockIdx.x, j = threadIdx.x;
    __shared__ float sh[16];
    __shared__ float s_mu, s_var;
    float v = g_h[b * HH + j];
    float s = v;
#pragma unroll
    for (int o = 16; o; o >>= 1) s += __shfl_xor_sync(0xffffffffu, s, o);
    if ((j & 31) == 0) sh[j >> 5] = s;
    __syncthreads();
    if (j == 0) { float t = 0.f; for (int w = 0; w < 16; w++) t += sh[w]; s_mu = t / HH; }
    __syncthreads();
    float d = v - s_mu;
    float s2 = d * d;
#pragma unroll
    for (int o = 16; o; o >>= 1) s2 += __shfl_xor_sync(0xffffffffu, s2, o);
    __syncthreads();
    if ((j & 31) == 0) sh[j >> 5] = s2;
    __syncthreads();
    if (j == 0) { float t = 0.f; for (int w = 0; w < 16; w++) t += sh[w]; s_var = t / HH; }
    __syncthreads();
    g_h[b * HH + j] = d * rsqrtf(s_var + 1e-5f) * gamma[j] + beta[j];
}

// ---------------- exact top-k set selection via counting rank ----------------
__global__ void k_select(const float* __restrict__ vals, int n, int k, int* __restrict__ idx) {
    int b = blockIdx.y;
    const float* v = vals + (size_t)b * n;
    int i = blockIdx.x * 256 + threadIdx.x;
    float vi = v[i];
    __shared__ float sv[256];
    int r = 0;
    for (int t0 = 0; t0 < n; t0 += 256) {
        sv[threadIdx.x] = v[t0 + threadIdx.x];
        __syncthreads();
#pragma unroll 8
        for (int t = 0; t < 256; t++) {
            float vj = sv[t];
            int j = t0 + t;
            r += (vj > vi) || (vj == vi && j < i);
        }
        __syncthreads();
    }
    if (r < k) idx[(size_t)b * k + r] = i;
}

// ---------------- sort selected index list ascending (set is order-invariant) ----
__global__ void k_order(const int* __restrict__ in, int* __restrict__ outp, int k) {
    int b = blockIdx.y;
    const int* v = in + (size_t)b * k;
    int i = blockIdx.x * 256 + threadIdx.x;
    int vi = v[i];
    __shared__ int sv[256];
    int cnt = 0;
    for (int t0 = 0; t0 < k; t0 += 256) {
        sv[threadIdx.x] = v[t0 + threadIdx.x];
        __syncthreads();
#pragma unroll 8
        for (int t = 0; t < 256; t++) cnt += (sv[t] < vi);
        __syncthreads();
    }
    outp[(size_t)b * k + cnt] = vi;
}

// ---------------- gather process weight columns: Wg[b][p][k] = PW[p][iidx2[b][k]] --
__global__ void k_gatherW(const float* __restrict__ PW) {
    int b = blockIdx.z;
    int k0 = blockIdx.x * 256;
    int p0 = blockIdx.y * 32;
    __shared__ int si[256];
    si[threadIdx.x] = g_iidx2[(size_t)b * KIN + k0 + threadIdx.x];
    __syncthreads();
    int col = si[threadIdx.x];
#pragma unroll 4
    for (int pp = 0; pp < 32; pp++) {
        int p = p0 + pp;
        g_Wg[((size_t)b * NPROC + p) * KIN + k0 + threadIdx.x] = PW[(size_t)p * NIN + col];
    }
}

// ---------------- scores[b][p] = mean_s proc[b][s][p] ----------------
__global__ void k_scores() {
    int b = blockIdx.y;
    int p = blockIdx.x * 256 + threadIdx.x;
    const float* base = g_proc + (size_t)b * SS * NPROC + p;
    float s = 0.f;
    for (int t = 0; t < SS; t++) s += base[(size_t)t * NPROC];
    g_scores[b * NPROC + p] = s * (1.0f / SS);
}

// ---------------- gather selected proc columns ----------------
__global__ void k_gathersp() {
    int b = blockIdx.z, s = blockIdx.y;
    int k = blockIdx.x * 256 + threadIdx.x;
    int pi = g_pidx2[(size_t)b * KPROC + k];
    g_sp[((size_t)b * SS + s) * KPROC + k] = g_proc[((size_t)b * SS + s) * NPROC + pi];
}

// ---------------- gather+transpose process_outputs: POt[b][d][k] ----------------
__global__ void k_po_t(const float* __restrict__ PO) {
    __shared__ float t[32][33];
    int k0 = blockIdx.x * 32, d0 = blockIdx.y * 32, b = blockIdx.z;
    int tx = threadIdx.x & 31, ty = threadIdx.x >> 5;
    for (int i = ty; i < 32; i += 8) {
        int pi = g_pidx2[(size_t)b * KPROC + k0 + i];
        t[i][tx] = PO[(size_t)pi * DD + d0 + tx];
    }
    __syncthreads();
    for (int i = ty; i < 32; i += 8)
        g_pot[((size_t)b * DD + d0 + i) * KPROC + k0 + tx] = t[tx][i];
}

// ---------------- host side ----------------
extern "C" void kernel_launch(void* const* d_in, const int* in_sizes, int n_in,
                              void* d_out, int out_size) {
    const float* x   = (const float*)d_in[0];
    const float* W1  = (const float*)d_in[1];
    const float* b1  = (const float*)d_in[2];
    const float* lng = (const float*)d_in[3];
    const float* lnb = (const float*)d_in[4];
    const float* W2  = (const float*)d_in[5];
    const float* b2  = (const float*)d_in[6];
    const float* NK  = (const float*)d_in[7];
    const float* IP  = (const float*)d_in[8];
    const float* PW  = (const float*)d_in[9];
    const float* PO  = (const float*)d_in[10];
    float* out = (float*)d_out;

    void *p_gc, *p_h, *p_query, *p_logits, *p_iidx, *p_iidx2, *p_pidx, *p_pidx2, *p_scores;
    void *p_sel, *p_Wg, *p_proc, *p_sp, *p_pot;
    cudaGetSymbolAddress(&p_gc, g_gc);
    cudaGetSymbolAddress(&p_h, g_h);
    cudaGetSymbolAddress(&p_query, g_query);
    cudaGetSymbolAddress(&p_logits, g_logits);
    cudaGetSymbolAddress(&p_iidx, g_iidx);
    cudaGetSymbolAddress(&p_iidx2, g_iidx2);
    cudaGetSymbolAddress(&p_pidx, g_pidx);
    cudaGetSymbolAddress(&p_pidx2, g_pidx2);
    cudaGetSymbolAddress(&p_scores, g_scores);
    cudaGetSymbolAddress(&p_sel, g_sel);
    cudaGetSymbolAddress(&p_Wg, g_Wg);
    cudaGetSymbolAddress(&p_proc, g_proc);
    cudaGetSymbolAddress(&p_sp, g_sp);
    cudaGetSymbolAddress(&p_pot, g_pot);

    const int SMEM = 4 * TILE_F * 4;   // 73728 bytes
    cudaFuncSetAttribute((const void*)&k_gemm_mma<3, 1, 1>, cudaFuncAttributeMaxDynamicSharedMemorySize, SMEM);
    cudaFuncSetAttribute((const void*)&k_gemm_mma<3, 1, 0>, cudaFuncAttributeMaxDynamicSharedMemorySize, SMEM);
    cudaFuncSetAttribute((const void*)&k_gemm_mma<1, 0, 0>, cudaFuncAttributeMaxDynamicSharedMemorySize, SMEM);

    // 1) router
    k_gcmax<<<dim3(DD / 256, BB), 256>>>(x);
    k_matvec<<<(BB * HH) / 8, 256>>>(W1, b1, (const float*)p_gc, (float*)p_h, HH, DD, 1.0f, 1);
    k_ln<<<BB, HH>>>(lng, lnb);
    k_matvec<<<(BB * DR) / 8, 256>>>(W2, b2, (const float*)p_h, (float*)p_query, DR, HH, 1.0f, 0);
    k_matvec<<<(BB * NIN) / 8, 256>>>(NK, nullptr, (const float*)p_query, (float*)p_logits,
                                      NIN, DR, 0.0625f, 0);
    k_select<<<dim3(NIN / 256, BB), 256>>>((const float*)p_logits, NIN, KIN, (int*)p_iidx);
    k_order<<<dim3(KIN / 256, BB), 256>>>((const int*)p_iidx, (int*)p_iidx2, KIN);

    // 2) sel = gelu(x @ IP[iidx]^T), 3xTF32
    k_gemm_mma<3, 1, 1><<<dim3(KIN / 128, SS / 128, BB), 256, SMEM>>>(
        x, IP, (const int*)p_iidx2, (float*)p_sel,
        DD, KIN, (size_t)SS * DD, 0, (size_t)SS * KIN, KIN);

    // 3) Wg gather
    k_gatherW<<<dim3(KIN / 256, NPROC / 32, BB), 256>>>(PW);

    // 4) proc = gelu(sel @ Wg^T), 3xTF32
    k_gemm_mma<3, 1, 0><<<dim3(NPROC / 128, SS / 128, BB), 256, SMEM>>>(
        (const float*)p_sel, (const float*)p_Wg, nullptr, (float*)p_proc,
        KIN, NPROC, (size_t)SS * KIN, (size_t)NPROC * KIN, (size_t)SS * NPROC, 0);

    // 5) process selection
    k_scores<<<dim3(NPROC / 256, BB), 256>>>();
    k_select<<<dim3(NPROC / 256, BB), 256>>>((const float*)p_scores, NPROC, KPROC, (int*)p_pidx);
    k_order<<<dim3(KPROC / 256, BB), 256>>>((const int*)p_pidx, (int*)p_pidx2, KPROC);

    // 6) gathers for output GEMM
    k_gathersp<<<dim3(KPROC / 256, SS, BB), 256>>>();
    k_po_t<<<dim3(KPROC / 32, DD / 32, BB), 256>>>(PO);

    // 7) out = sp @ POt^T, 1xTF32
    k_gemm_mma<1, 0, 0><<<dim3(DD / 128, SS / 128, BB), 256, SMEM>>>(
        (const float*)p_sp, (const float*)p_pot, nullptr, out,
        KPROC, DD, (size_t)SS * KPROC, (size_t)DD * KPROC, (size_t)SS * DD, 0);
}

// round 4
// speedup vs baseline: 1.4275x; 1.0246x over previous
#include <cuda_runtime.h>
#include <cuda_fp16.h>
#include <math.h>
#include <stdint.h>

#define BB     4
#define SS     2048
#define DD     1024
#define NIN    8192
#define NPROC  4096
#define DR     256
#define HH     512
#define KIN    4096
#define KPROC  2048

#define SCALE_B   4096.0f
#define INV_SCALE 2.44140625e-4f

// ---------------- scratch (static device memory; no allocs) ----------------
__device__ float g_gc[BB * DD];
__device__ float g_h[BB * HH];
__device__ float g_query[BB * DR];
__device__ float g_logits[BB * NIN];
__device__ int   g_iidx[BB * KIN];
__device__ int   g_iidx2[BB * KIN];
__device__ int   g_pidx[BB * KPROC];
__device__ int   g_pidx2[BB * KPROC];
__device__ float g_scores[BB * NPROC];

__align__(16) __device__ __half g_xh[(size_t)BB * SS * DD];
__align__(16) __device__ __half g_xl[(size_t)BB * SS * DD];
__align__(16) __device__ __half g_ipgh[(size_t)BB * KIN * DD];
__align__(16) __device__ __half g_ipgl[(size_t)BB * KIN * DD];
__align__(16) __device__ __half g_selh[(size_t)BB * SS * KIN];
__align__(16) __device__ __half g_sell[(size_t)BB * SS * KIN];
__align__(16) __device__ __half g_wgh[(size_t)BB * NPROC * KIN];
__align__(16) __device__ __half g_wgl[(size_t)BB * NPROC * KIN];
__align__(16) __device__ __half g_sph[(size_t)BB * SS * KPROC];
__align__(16) __device__ __half g_spl[(size_t)BB * SS * KPROC];
__align__(16) __device__ __half g_poth[(size_t)BB * DD * KPROC];
__align__(16) __device__ __half g_potl[(size_t)BB * DD * KPROC];
__device__ float g_proc[(size_t)BB * SS * NPROC];

__device__ __forceinline__ float gelu_f(float x) {
    return 0.5f * x * (1.0f + erff(x * 0.70710678118654752440f));
}
__device__ __forceinline__ void split16(float v, __half& h, __half& l) {
    h = __float2half_rn(v);
    l = __float2half_rn(v - __half2float(h));
}

__device__ __forceinline__ uint32_t s2u(const void* p) {
    uint32_t a;
    asm("{ .reg .u64 t; cvta.to.shared.u64 t, %1; cvt.u32.u64 %0, t; }" : "=r"(a) : "l"(p));
    return a;
}
__device__ __forceinline__ void cpa16h(uint32_t dst, const __half* src) {
    asm volatile("cp.async.cg.shared.global [%0], [%1], 16;" :: "r"(dst), "l"(src));
}
__device__ __forceinline__ void cpacommit() { asm volatile("cp.async.commit_group;" ::: "memory"); }
__device__ __forceinline__ void cpawait2()  { asm volatile("cp.async.wait_group 2;" ::: "memory"); }

__device__ __forceinline__ void ldsm4(uint32_t* r, uint32_t a) {
    asm volatile("ldmatrix.sync.aligned.m8n8.x4.shared.b16 {%0,%1,%2,%3}, [%4];"
        : "=r"(r[0]), "=r"(r[1]), "=r"(r[2]), "=r"(r[3]) : "r"(a));
}
__device__ __forceinline__ void mma16(float* c, const uint32_t* a, const uint32_t* b) {
    asm volatile("mma.sync.aligned.m16n8k16.row.col.f32.f16.f16.f32 "
        "{%0,%1,%2,%3}, {%4,%5,%6,%7}, {%8,%9}, {%0,%1,%2,%3};"
        : "+f"(c[0]), "+f"(c[1]), "+f"(c[2]), "+f"(c[3])
        : "r"(a[0]), "r"(a[1]), "r"(a[2]), "r"(a[3]), "r"(b[0]), "r"(b[1]));
}

// ============ fp16 3-term split GEMM: C[128m x 128n], NT, hi/lo planes ============
#define SPAD   80                  // smem row pitch bytes (32 data halves + pad)
#define PLANE  10240               // 128 * 80
#define OFF_AL PLANE
#define OFF_BH (2 * PLANE)
#define OFF_BL (3 * PLANE)
#define STG    (4 * PLANE)         // 40960 per stage
#define SMEM_T (4 * STG)           // 4 stages = 163840

template <int ACT, int SPLIT>
__global__ void __launch_bounds__(256, 1)
k_gemm_h(const __half* __restrict__ Ah, const __half* __restrict__ Al,
         const __half* __restrict__ Bh, const __half* __restrict__ Bl,
         void* __restrict__ C0v, void* __restrict__ C1v,
         int K, int ldc, size_t aB, size_t bB, size_t cB) {
    extern __shared__ char smem[];
    const int tid = threadIdx.x, bz = blockIdx.z;
    const int m0 = blockIdx.y * 128, n0 = blockIdx.x * 128;
    Ah += bz * aB + (size_t)m0 * K;
    Al += bz * aB + (size_t)m0 * K;
    Bh += bz * bB + (size_t)n0 * K;
    Bl += bz * bB + (size_t)n0 * K;
    const uint32_t s0 = s2u(smem);

    // loader: thread -> rows (tid>>2, +64), 16B group (tid&3)
    const int lr = tid >> 2, lg = tid & 3;
    const size_t go0 = (size_t)lr * K + lg * 8;
    const size_t go1 = go0 + (size_t)64 * K;
    const uint32_t so0 = (uint32_t)(lr * SPAD + lg * 16);
    const uint32_t so1 = so0 + 64 * SPAD;

    // fragment addresses
    const int lane = tid & 31, wid = tid >> 5;
    const int wm = (wid & 1) * 64, wn = (wid >> 1) * 32;
    const int l8 = lane & 7, mid = lane >> 3;
    uint32_t aoff[4][2], boff[2][2];
#pragma unroll
    for (int mt = 0; mt < 4; mt++)
#pragma unroll
        for (int ks = 0; ks < 2; ks++)
            aoff[mt][ks] = (uint32_t)((wm + mt * 16 + (mid & 1) * 8 + l8) * SPAD
                                      + ((mid >> 1) * 8 + ks * 16) * 2);
#pragma unroll
    for (int p = 0; p < 2; p++)
#pragma unroll
        for (int ks = 0; ks < 2; ks++)
            boff[p][ks] = (uint32_t)(OFF_BH + (wn + p * 16 + (mid >> 1) * 8 + l8) * SPAD
                                     + ((mid & 1) * 8 + ks * 16) * 2);

    float acc[4][4][4];
#pragma unroll
    for (int mt = 0; mt < 4; mt++)
#pragma unroll
        for (int nt = 0; nt < 4; nt++)
#pragma unroll
            for (int e = 0; e < 4; e++) acc[mt][nt][e] = 0.f;

    const int nc = K >> 5;

#define LOADSTG(c) do { \
    uint32_t sb_ = s0 + ((c) & 3) * STG; \
    size_t ko_ = (size_t)(c) * 32; \
    cpa16h(sb_ + so0,          Ah + go0 + ko_); \
    cpa16h(sb_ + so1,          Ah + go1 + ko_); \
    cpa16h(sb_ + OFF_AL + so0, Al + go0 + ko_); \
    cpa16h(sb_ + OFF_AL + so1, Al + go1 + ko_); \
    cpa16h(sb_ + OFF_BH + so0, Bh + go0 + ko_); \
    cpa16h(sb_ + OFF_BH + so1, Bh + go1 + ko_); \
    cpa16h(sb_ + OFF_BL + so0, Bl + go0 + ko_); \
    cpa16h(sb_ + OFF_BL + so1, Bl + go1 + ko_); \
    cpacommit(); \
} while (0)

    LOADSTG(0); LOADSTG(1); LOADSTG(2);

    for (int c = 0; c < nc; c++) {
        cpawait2();
        __syncthreads();
        if (c + 3 < nc) LOADSTG(c + 3); else cpacommit();
        const uint32_t sb = s0 + (c & 3) * STG;
#pragma unroll
        for (int ks = 0; ks < 2; ks++) {
            uint32_t fa[4][4], fal[4][4], fb[2][4], fbl[2][4];
#pragma unroll
            for (int mt = 0; mt < 4; mt++) ldsm4(fa[mt], sb + aoff[mt][ks]);
#pragma unroll
            for (int mt = 0; mt < 4; mt++) ldsm4(fal[mt], sb + OFF_AL + aoff[mt][ks]);
#pragma unroll
            for (int p = 0; p < 2; p++) ldsm4(fb[p], sb + boff[p][ks]);
#pragma unroll
            for (int p = 0; p < 2; p++) ldsm4(fbl[p], sb + PLANE + boff[p][ks]);
            // pass-major order: same-acc reuse distance = 16 MMAs
#pragma unroll
            for (int mt = 0; mt < 4; mt++)
#pragma unroll
                for (int nt = 0; nt < 4; nt++)
                    mma16(acc[mt][nt], fa[mt], &fb[nt >> 1][(nt & 1) * 2]);
#pragma unroll
            for (int mt = 0; mt < 4; mt++)
#pragma unroll
                for (int nt = 0; nt < 4; nt++)
                    mma16(acc[mt][nt], fa[mt], &fbl[nt >> 1][(nt & 1) * 2]);
#pragma unroll
            for (int mt = 0; mt < 4; mt++)
#pragma unroll
                for (int nt = 0; nt < 4; nt++)
                    mma16(acc[mt][nt], fal[mt], &fb[nt >> 1][(nt & 1) * 2]);
        }
    }
#undef LOADSTG

    // epilogue
    const int qr = lane >> 2, qk = lane & 3;
#pragma unroll
    for (int mt = 0; mt < 4; mt++) {
#pragma unroll
        for (int nt = 0; nt < 4; nt++) {
            const int r = m0 + wm + mt * 16 + qr;
            const int cc = n0 + wn + nt * 8 + qk * 2;
            float v0 = acc[mt][nt][0] * INV_SCALE;
            float v1 = acc[mt][nt][1] * INV_SCALE;
            float v2 = acc[mt][nt][2] * INV_SCALE;
            float v3 = acc[mt][nt][3] * INV_SCALE;
            if (ACT) { v0 = gelu_f(v0); v1 = gelu_f(v1); v2 = gelu_f(v2); v3 = gelu_f(v3); }
            if (SPLIT) {
                __half* C0 = (__half*)C0v + bz * cB;
                __half* C1 = (__half*)C1v + bz * cB;
                __half h0, l0, h1, l1;
                split16(v0, h0, l0); split16(v1, h1, l1);
                *(__half2*)&C0[(size_t)r * ldc + cc] = __halves2half2(h0, h1);
                *(__half2*)&C1[(size_t)r * ldc + cc] = __halves2half2(l0, l1);
                split16(v2, h0, l0); split16(v3, h1, l1);
                *(__half2*)&C0[(size_t)(r + 8) * ldc + cc] = __halves2half2(h0, h1);
                *(__half2*)&C1[(size_t)(r + 8) * ldc + cc] = __halves2half2(l0, l1);
            } else {
                float* C0 = (float*)C0v + bz * cB;
                float2 w0 = {v0, v1}, w1 = {v2, v3};
                *(float2*)&C0[(size_t)r * ldc + cc] = w0;
                *(float2*)&C0[(size_t)(r + 8) * ldc + cc] = w1;
            }
        }
    }
}

// ---------------- router / selection kernels ----------------
__global__ void k_gcmax(const float* __restrict__ x) {
    int b = blockIdx.y;
    int d = blockIdx.x * 256 + threadIdx.x;
    const float* p = x + (size_t)b * SS * DD + d;
    float m = -3.4e38f;
    for (int s = 0; s < SS; s++) m = fmaxf(m, p[(size_t)s * DD]);
    g_gc[b * DD + d] = m;
}

__global__ void k_matvec(const float* __restrict__ W, const float* __restrict__ bias,
                         const float* __restrict__ in, float* __restrict__ out,
                         int Nout, int Kd, float scale, int act) {
    int o = blockIdx.x * 8 + (threadIdx.x >> 5);
    int lane = threadIdx.x & 31;
    if (o >= BB * Nout) return;
    int b = o / Nout, j = o - b * Nout;
    const float* w = W + (size_t)j * Kd;
    const float* v = in + (size_t)b * Kd;
    float s = 0.f;
    for (int d = lane; d < Kd; d += 32) s = fmaf(w[d], v[d], s);
#pragma unroll
    for (int off = 16; off; off >>= 1) s += __shfl_xor_sync(0xffffffffu, s, off);
    if (lane == 0) {
        s = s * scale + (bias ? bias[j] : 0.f);
        if (act) s = gelu_f(s);
        out[o] = s;
    }
}

__global__ void k_ln(const float* __restrict__ gamma, const float* __restrict__ beta) {
    int b = blockIdx.x, j = threadIdx.x;
    __shared__ float sh[16];
    __shared__ float s_mu, s_var;
    float v = g_h[b * HH + j];
    float s = v;
#pragma unroll
    for (int o = 16; o; o >>= 1) s += __shfl_xor_sync(0xffffffffu, s, o);
    if ((j & 31) == 0) sh[j >> 5] = s;
    __syncthreads();
    if (j == 0) { float t = 0.f; for (int w = 0; w < 16; w++) t += sh[w]; s_mu = t / HH; }
    __syncthreads();
    float d = v - s_mu;
    float s2 = d * d;
#pragma unroll
    for (int o = 16; o; o >>= 1) s2 += __shfl_xor_sync(0xffffffffu, s2, o);
    __syncthreads();
    if ((j & 31) == 0) sh[j >> 5] = s2;
    __syncthreads();
    if (j == 0) { float t = 0.f; for (int w = 0; w < 16; w++) t += sh[w]; s_var = t / HH; }
    __syncthreads();
    g_h[b * HH + j] = d * rsqrtf(s_var + 1e-5f) * gamma[j] + beta[j];
}

__global__ void k_select(const float* __restrict__ vals, int n, int k, int* __restrict__ idx) {
    int b = blockIdx.y;
    const float* v = vals + (size_t)b * n;
    int i = blockIdx.x * 256 + threadIdx.x;
    float vi = v[i];
    __shared__ float sv[256];
    int r = 0;
    for (int t0 = 0; t0 < n; t0 += 256) {
        sv[threadIdx.x] = v[t0 + threadIdx.x];
        __syncthreads();
#pragma unroll 8
        for (int t = 0; t < 256; t++) {
            float vj = sv[t];
            int j = t0 + t;
            r += (vj > vi) || (vj == vi && j < i);
        }
        __syncthreads();
    }
    if (r < k) idx[(size_t)b * k + r] = i;
}

__global__ void k_order(const int* __restrict__ in, int* __restrict__ outp, int k) {
    int b = blockIdx.y;
    const int* v = in + (size_t)b * k;
    int i = blockIdx.x * 256 + threadIdx.x;
    int vi = v[i];
    __shared__ int sv[256];
    int cnt = 0;
    for (int t0 = 0; t0 < k; t0 += 256) {
        sv[threadIdx.x] = v[t0 + threadIdx.x];
        __syncthreads();
#pragma unroll 8
        for (int t = 0; t < 256; t++) cnt += (sv[t] < vi);
        __syncthreads();
    }
    outp[(size_t)b * k + cnt] = vi;
}

// ---------------- prepass: f32 -> fp16 hi/lo planes (optionally scaled) ----------
__global__ void k_split16v(const float* __restrict__ in, __half* __restrict__ oh,
                           __half* __restrict__ ol, float scale) {
    size_t i = (size_t)blockIdx.x * 256 + threadIdx.x;
    float4 v = ((const float4*)in)[i];
    __half hx, lx, hy, ly, hz, lz, hw, lw;
    split16(v.x * scale, hx, lx); split16(v.y * scale, hy, ly);
    split16(v.z * scale, hz, lz); split16(v.w * scale, hw, lw);
    ((__half2*)oh)[2 * i]     = __halves2half2(hx, hy);
    ((__half2*)oh)[2 * i + 1] = __halves2half2(hz, hw);
    ((__half2*)ol)[2 * i]     = __halves2half2(lx, ly);
    ((__half2*)ol)[2 * i + 1] = __halves2half2(lz, lw);
}

// gather IP rows (sorted idx) + scale + split
__global__ void k_gather_ip(const float* __restrict__ IP) {
    int b = blockIdx.y, kk = blockIdx.x;
    int col = g_iidx2[(size_t)b * KIN + kk];
    const float4* src = (const float4*)(IP + (size_t)col * DD);
    __half2* dh = (__half2*)(g_ipgh + ((size_t)b * KIN + kk) * DD);
    __half2* dl = (__half2*)(g_ipgl + ((size_t)b * KIN + kk) * DD);
    int d = threadIdx.x;
    float4 v = src[d];
    __half hx, lx, hy, ly, hz, lz, hw, lw;
    split16(v.x * SCALE_B, hx, lx); split16(v.y * SCALE_B, hy, ly);
    split16(v.z * SCALE_B, hz, lz); split16(v.w * SCALE_B, hw, lw);
    dh[2 * d] = __halves2half2(hx, hy); dh[2 * d + 1] = __halves2half2(hz, hw);
    dl[2 * d] = __halves2half2(lx, ly); dl[2 * d + 1] = __halves2half2(lz, lw);
}

// gather PW columns + scale + split: wg[b][p][k] = PW[p][iidx2[b][k]] * SCALE
__global__ void k_gatherW(const float* __restrict__ PW) {
    int b = blockIdx.z;
    int k0 = blockIdx.x * 256;
    int p0 = blockIdx.y * 32;
    __shared__ int si[256];
    si[threadIdx.x] = g_iidx2[(size_t)b * KIN + k0 + threadIdx.x];
    __syncthreads();
    int col = si[threadIdx.x];
#pragma unroll 4
    for (int pp = 0; pp < 32; pp++) {
        int p = p0 + pp;
        float v = PW[(size_t)p * NIN + col] * SCALE_B;
        __half h, l;
        split16(v, h, l);
        size_t o = ((size_t)b * NPROC + p) * KIN + k0 + threadIdx.x;
        g_wgh[o] = h;
        g_wgl[o] = l;
    }
}

__global__ void k_scores() {
    int b = blockIdx.y;
    int p = blockIdx.x * 256 + threadIdx.x;
    const float* base = g_proc + (size_t)b * SS * NPROC + p;
    float s = 0.f;
    for (int t = 0; t < SS; t++) s += base[(size_t)t * NPROC];
    g_scores[b * NPROC + p] = s * (1.0f / SS);
}

// gather selected proc columns -> sp hi/lo planes (no scale: A-side)
__global__ void k_gathersp() {
    int b = blockIdx.z, s = blockIdx.y;
    int k = blockIdx.x * 256 + threadIdx.x;
    int pi = g_pidx2[(size_t)b * KPROC + k];
    float v = g_proc[((size_t)b * SS + s) * NPROC + pi];
    __half h, l;
    split16(v, h, l);
    g_sph[((size_t)b * SS + s) * KPROC + k] = h;
    g_spl[((size_t)b * SS + s) * KPROC + k] = l;
}

// gather+transpose PO: pot[b][d][k] = PO[pidx2[b][k]][d] * SCALE, split
__global__ void k_po_t(const float* __restrict__ PO) {
    __shared__ float t[32][33];
    int k0 = blockIdx.x * 32, d0 = blockIdx.y * 32, b = blockIdx.z;
    int tx = threadIdx.x & 31, ty = threadIdx.x >> 5;
    for (int i = ty; i < 32; i += 8) {
        int pi = g_pidx2[(size_t)b * KPROC + k0 + i];
        t[i][tx] = PO[(size_t)pi * DD + d0 + tx];
    }
    __syncthreads();
    for (int i = ty; i < 32; i += 8) {
        float v = t[tx][i] * SCALE_B;
        __half h, l;
        split16(v, h, l);
        size_t o = ((size_t)b * DD + d0 + i) * KPROC + k0 + tx;
        g_poth[o] = h;
        g_potl[o] = l;
    }
}

// ---------------- host side ----------------
extern "C" void kernel_launch(void* const* d_in, const int* in_sizes, int n_in,
                              void* d_out, int out_size) {
    const float* x   = (const float*)d_in[0];
    const float* W1  = (const float*)d_in[1];
    const float* b1  = (const float*)d_in[2];
    const float* lng = (const float*)d_in[3];
    const float* lnb = (const float*)d_in[4];
    const float* W2  = (const float*)d_in[5];
    const float* b2  = (const float*)d_in[6];
    const float* NK  = (const float*)d_in[7];
    const float* IP  = (const float*)d_in[8];
    const float* PW  = (const float*)d_in[9];
    const float* PO  = (const float*)d_in[10];
    float* out = (float*)d_out;

    void *p_gc, *p_h, *p_query, *p_logits, *p_iidx, *p_iidx2, *p_pidx, *p_pidx2, *p_scores;
    void *p_xh, *p_xl, *p_ipgh, *p_ipgl, *p_selh, *p_sell, *p_wgh, *p_wgl;
    void *p_proc, *p_sph, *p_spl, *p_poth, *p_potl;
    cudaGetSymbolAddress(&p_gc, g_gc);
    cudaGetSymbolAddress(&p_h, g_h);
    cudaGetSymbolAddress(&p_query, g_query);
    cudaGetSymbolAddress(&p_logits, g_logits);
    cudaGetSymbolAddress(&p_iidx, g_iidx);
    cudaGetSymbolAddress(&p_iidx2, g_iidx2);
    cudaGetSymbolAddress(&p_pidx, g_pidx);
    cudaGetSymbolAddress(&p_pidx2, g_pidx2);
    cudaGetSymbolAddress(&p_scores, g_scores);
    cudaGetSymbolAddress(&p_xh, g_xh);
    cudaGetSymbolAddress(&p_xl, g_xl);
    cudaGetSymbolAddress(&p_ipgh, g_ipgh);
    cudaGetSymbolAddress(&p_ipgl, g_ipgl);
    cudaGetSymbolAddress(&p_selh, g_selh);
    cudaGetSymbolAddress(&p_sell, g_sell);
    cudaGetSymbolAddress(&p_wgh, g_wgh);
    cudaGetSymbolAddress(&p_wgl, g_wgl);
    cudaGetSymbolAddress(&p_proc, g_proc);
    cudaGetSymbolAddress(&p_sph, g_sph);
    cudaGetSymbolAddress(&p_spl, g_spl);
    cudaGetSymbolAddress(&p_poth, g_poth);
    cudaGetSymbolAddress(&p_potl, g_potl);

    cudaFuncSetAttribute((const void*)&k_gemm_h<1, 1>, cudaFuncAttributeMaxDynamicSharedMemorySize, SMEM_T);
    cudaFuncSetAttribute((const void*)&k_gemm_h<1, 0>, cudaFuncAttributeMaxDynamicSharedMemorySize, SMEM_T);
    cudaFuncSetAttribute((const void*)&k_gemm_h<0, 0>, cudaFuncAttributeMaxDynamicSharedMemorySize, SMEM_T);

    // 1) router
    k_gcmax<<<dim3(DD / 256, BB), 256>>>(x);
    k_matvec<<<(BB * HH) / 8, 256>>>(W1, b1, (const float*)p_gc, (float*)p_h, HH, DD, 1.0f, 1);
    k_ln<<<BB, HH>>>(lng, lnb);
    k_matvec<<<(BB * DR) / 8, 256>>>(W2, b2, (const float*)p_h, (float*)p_query, DR, HH, 1.0f, 0);
    k_matvec<<<(BB * NIN) / 8, 256>>>(NK, nullptr, (const float*)p_query, (float*)p_logits,
                                      NIN, DR, 0.0625f, 0);
    k_select<<<dim3(NIN / 256, BB), 256>>>((const float*)p_logits, NIN, KIN, (int*)p_iidx);
    k_order<<<dim3(KIN / 256, BB), 256>>>((const int*)p_iidx, (int*)p_iidx2, KIN);

    // 2) operand prep for sel GEMM
    k_split16v<<<(size_t)BB * SS * DD / 4 / 256, 256>>>(x, (__half*)p_xh, (__half*)p_xl, 1.0f);
    k_gather_ip<<<dim3(KIN, BB), 256>>>(IP);

    // 3) sel = gelu((x @ IPg^T)/S), 3xFP16, epilogue writes fp16 hi/lo planes
    k_gemm_h<1, 1><<<dim3(KIN / 128, SS / 128, BB), 256, SMEM_T>>>(
        (const __half*)p_xh, (const __half*)p_xl, (const __half*)p_ipgh, (const __half*)p_ipgl,
        p_selh, p_sell, DD, KIN,
        (size_t)SS * DD, (size_t)KIN * DD, (size_t)SS * KIN);

    // 4) Wg gather + split
    k_gatherW<<<dim3(KIN / 256, NPROC / 32, BB), 256>>>(PW);

    // 5) proc = gelu((sel @ Wg^T)/S), 3xFP16 -> fp32
    k_gemm_h<1, 0><<<dim3(NPROC / 128, SS / 128, BB), 256, SMEM_T>>>(
        (const __half*)p_selh, (const __half*)p_sell, (const __half*)p_wgh, (const __half*)p_wgl,
        p_proc, nullptr, KIN, NPROC,
        (size_t)SS * KIN, (size_t)NPROC * KIN, (size_t)SS * NPROC);

    // 6) process selection
    k_scores<<<dim3(NPROC / 256, BB), 256>>>();
    k_select<<<dim3(NPROC / 256, BB), 256>>>((const float*)p_scores, NPROC, KPROC, (int*)p_pidx);
    k_order<<<dim3(KPROC / 256, BB), 256>>>((const int*)p_pidx, (int*)p_pidx2, KPROC);

    // 7) gathers for output GEMM
    k_gathersp<<<dim3(KPROC / 256, SS, BB), 256>>>();
    k_po_t<<<dim3(KPROC / 32, DD / 32, BB), 256>>>(PO);

    // 8) out = (sp @ POt^T)/S, 3xFP16 -> fp32
    k_gemm_h<0, 0><<<dim3(DD / 128, SS / 128, BB), 256, SMEM_T>>>(
        (const __half*)p_sph, (const __half*)p_spl, (const __half*)p_poth, (const __half*)p_potl,
        out, nullptr, KPROC, DD,
        (size_t)SS * KPROC, (size_t)DD * KPROC, (size_t)SS * DD);
}